// round 11
// baseline (speedup 1.0000x reference)
#include <cuda_runtime.h>
#include <cuda_fp16.h>
#include <cstdint>

#define Tt 3
#define Ll 4
#define Mm 3
#define Bb 8
#define Cc 64
#define Hh 128
#define Ww 128
#define HWp (Hh*Ww)
#define PW 130
#define PPX (PW*PW)              // 16900 padded pixels
#define FRONT 256
#define SLACK 384
#define PTOT (FRONT + PPX + SLACK)

#define TILE_M 256
#define HALO 131                 // PW + 1
#define STRIP_PX (TILE_M + 2*HALO)   // 518
#define STRIP_B (STRIP_PX*128)       // 66304 bytes
#define TILES 67                 // ceil(PPX/TILE_M)
#define CTAS 148
#define JOBS (Tt*Bb*TILES)       // 1608 jobs per layer
#define NT 128                   // threads per conv CTA (4 warps)

#define SW_OFF 0                 // weights: 9 taps x 8192 B = 73728
#define SA0_OFF 73728            // A buffer 0: 66304 B
#define SA1_OFF (SA0_OFF + STRIP_B)  // 140032
#define SMEM_TOT (SA1_OFF + STRIP_B + 128) // 206464

// ---------------- device state ----------------
__device__ int g_sel[Tt*Ll];
// weights fp16: [mod 12][tap 9][oc 64][ic 64]
__device__ __align__(256) __half g_wH[(size_t)12*9*64*64];
// layer-0 input, padded NHWC fp16: [b][PTOT][64]
__device__ __align__(256) __half g_xp[(size_t)Bb*PTOT*Cc];
// ping-pong activations: [pp 2][t*b 24][PTOT][64]
__device__ __align__(256) __half g_act[2][(size_t)Tt*Bb*PTOT*Cc];

// ---------------- helpers ----------------
__device__ __forceinline__ uint32_t smem_u32(const void* p) {
    uint32_t a;
    asm("{ .reg .u64 t; cvta.to.shared.u64 t, %1; cvt.u32.u64 %0, t; }" : "=r"(a) : "l"(p));
    return a;
}
__device__ __forceinline__ void cp16(uint32_t sdst, const void* gsrc) {
    asm volatile("cp.async.cg.shared.global [%0], [%1], 16;" :: "r"(sdst), "l"(gsrc) : "memory");
}
__device__ __forceinline__ void cp_commit() { asm volatile("cp.async.commit_group;" ::: "memory"); }
template <int N>
__device__ __forceinline__ void cp_wait() {
    asm volatile("cp.async.wait_group %0;" :: "n"(N) : "memory");
}

__device__ __forceinline__ void ldmx4(uint32_t* r, uint32_t addr) {
    asm volatile("ldmatrix.sync.aligned.m8n8.x4.shared.b16 {%0,%1,%2,%3}, [%4];"
                 : "=r"(r[0]), "=r"(r[1]), "=r"(r[2]), "=r"(r[3]) : "r"(addr));
}
__device__ __forceinline__ void mma16816(float* c, const uint32_t* a, const uint32_t* b) {
    asm volatile("mma.sync.aligned.m16n8k16.row.col.f32.f16.f16.f32 "
                 "{%0,%1,%2,%3}, {%4,%5,%6,%7}, {%8,%9}, {%0,%1,%2,%3};"
                 : "+f"(c[0]), "+f"(c[1]), "+f"(c[2]), "+f"(c[3])
                 : "r"(a[0]), "r"(a[1]), "r"(a[2]), "r"(a[3]), "r"(b[0]), "r"(b[1]));
}

// ---------------- fused prep kernel ----------------------------------------
__global__ void __launch_bounds__(256) prep_kernel(
    const float* __restrict__ x, const float* __restrict__ alpha0,
    const float* __restrict__ alphas, const float* __restrict__ g0,
    const float* __restrict__ gs, const float* __restrict__ enc_w)
{
    const int bid = blockIdx.x;
    const int tid = threadIdx.x;

    if (bid < 128) {
        // ---- xprep: NCHW fp32 -> padded NHWC fp16, 4 px per thread ----
        int idx = bid * 256 + tid;            // [0, 32768)
        int b = idx >> 12;
        int pg = idx & 4095;
        int px0 = pg * 4;
        int y = px0 >> 7, x0 = px0 & 127;
        int p0 = (y + 1) * PW + (x0 + 1);
        const float* xs = x + ((size_t)b * Cc << 14) + px0;
        __half* dh = g_xp + ((size_t)b * PTOT + FRONT + p0) * Cc;
        #pragma unroll
        for (int g = 0; g < 8; g++) {
            float4 v[8];
            #pragma unroll
            for (int j = 0; j < 8; j++)
                v[j] = *reinterpret_cast<const float4*>(xs + (size_t)(g*8 + j) * HWp);
            #pragma unroll
            for (int e = 0; e < 4; e++) {
                uint32_t hv[4];
                #pragma unroll
                for (int q = 0; q < 4; q++) {
                    __half2 h = __floats2half2_rn((&v[q*2].x)[e], (&v[q*2+1].x)[e]);
                    hv[q] = *reinterpret_cast<uint32_t*>(&h);
                }
                *reinterpret_cast<uint4*>(dh + (size_t)e * Cc + g*8) =
                    make_uint4(hv[0], hv[1], hv[2], hv[3]);
            }
        }
    } else if (bid < 1856) {
        // ---- wprep: OIHW fp32 -> [mod][tap][oc][ic] fp16 ----
        int i = (bid - 128) * 256 + tid;       // [0, 442368)
        int ic  = i & 63;
        int oc  = (i >> 6) & 63;
        int tap = (i >> 12) % 9;
        int mod = i / 36864;
        float w = enc_w[(((size_t)(mod*Cc + oc))*Cc + ic)*9 + tap];
        g_wH[(((size_t)mod*9 + tap)*64 + oc)*64 + ic] = __float2half_rn(w);
    } else if (bid < 2109) {
        // ---- zero border pixels of 56 padded planes (8 xp + 48 act) ----
        int item = (bid - 1856) * 256 + tid;
        if (item >= 56 * 1156) return;
        int plane = item / 1156;
        int bi = item - plane * 1156;
        int px;
        if (bi < 256) px = bi;
        else {
            bi -= 256;
            if (bi < 130) px = FRONT + bi;
            else {
                bi -= 130;
                if (bi < 256) { int r = bi >> 1, c = bi & 1; px = FRONT + (r+1)*PW + c*129; }
                else {
                    bi -= 256;
                    if (bi < 130) px = FRONT + 129*PW + bi;
                    else px = FRONT + PPX + (bi - 130);
                }
            }
        }
        __half* base;
        if (plane < 8) base = g_xp + (size_t)plane * PTOT * Cc;
        else {
            int k = plane - 8;
            base = g_act[k / 24] + (size_t)(k % 24) * PTOT * Cc;
        }
        uint4 z = make_uint4(0, 0, 0, 0);
        uint4* d = (uint4*)(base + (size_t)px * Cc);
        #pragma unroll
        for (int q = 0; q < 8; q++) d[q] = z;
    } else {
        // ---- routing ----
        int t = tid;
        if (t >= Tt) return;
        int idx = 0;
        {
            float best = -1e30f; int bi2 = 0;
            #pragma unroll
            for (int m = 0; m < Mm; m++) {
                float v = alpha0[t*Mm + m] + g0[t*Mm + m];
                if (v > best) { best = v; bi2 = m; }
            }
            idx = bi2; g_sel[t*Ll + 0] = bi2;
        }
        for (int l = 1; l < Ll; l++) {
            const float* a = alphas + ((((size_t)(l-1)*Tt + t)*Mm + idx)*Mm);
            const float* g = gs     + ((((size_t)(l-1)*Tt + t)*Mm + idx)*Mm);
            float best = -1e30f; int bi2 = 0;
            #pragma unroll
            for (int m = 0; m < Mm; m++) {
                float v = a[m] + g[m];
                if (v > best) { best = v; bi2 = m; }
            }
            idx = bi2; g_sel[t*Ll + l] = bi2;
        }
    }
}

// ---------------- conv pass: 9 taps x 4 k, warp = M64 x N64 ----------------
__device__ __forceinline__ void conv_pass(float (*acc)[8][4], uint32_t sb,
                                          uint32_t abuf, int lane, int wm) {
    const int arow = lane & 15;
    const int akhalf = (lane >> 4) << 4;
    const int ocl = (lane & 7) + ((lane >> 4) << 3);
    const int bkhalf = ((lane >> 3) & 1) << 4;

    int obase[4], oxor[4];
    #pragma unroll
    for (int pr = 0; pr < 4; pr++) {
        int oc = pr * 16 + ocl;
        obase[pr] = oc * 128;
        oxor[pr] = (oc & 7) << 4;
    }

    #pragma unroll
    for (int tap = 0; tap < 9; tap++) {
        const int dy = tap / 3 - 1, dx = tap % 3 - 1;
        const int pxoff = HALO + dy * PW + dx;
        const uint32_t bb = sb + SW_OFF + tap * 8192;

        int abase[4], axor[4];
        #pragma unroll
        for (int mt = 0; mt < 4; mt++) {
            int px = wm * 64 + mt * 16 + arow + pxoff;
            abase[mt] = px * 128;
            axor[mt] = (px & 7) << 4;
        }

        #pragma unroll
        for (int k = 0; k < 4; k++) {
            uint32_t bh[8][2];
            #pragma unroll
            for (int pr = 0; pr < 4; pr++) {
                uint32_t off = obase[pr] + (uint32_t)((k * 32 + bkhalf) ^ oxor[pr]);
                uint32_t r[4];
                ldmx4(r, bb + off);
                bh[pr*2][0] = r[0]; bh[pr*2][1] = r[1];
                bh[pr*2+1][0] = r[2]; bh[pr*2+1][1] = r[3];
            }
            uint32_t aF[4][4];
            #pragma unroll
            for (int mt = 0; mt < 4; mt++) {
                uint32_t off = abase[mt] + (uint32_t)((k * 32 + akhalf) ^ axor[mt]);
                ldmx4(aF[mt], abuf + off);
            }
            #pragma unroll
            for (int mt = 0; mt < 4; mt++)
                #pragma unroll
                for (int nt = 0; nt < 8; nt++)
                    mma16816(acc[mt][nt], aF[mt], bh[nt]);
        }
    }
}

// ---------------- conv layer kernel ----------------------------------------
__global__ void __launch_bounds__(NT, 1) conv_hmma(
    int layer, int l0, int ps, int pd,
    const float* __restrict__ enc_b,
    const float* __restrict__ dec_w, const float* __restrict__ dec_b,
    float* __restrict__ out)
{
    extern __shared__ __align__(1024) char smem[];
    const uint32_t sb = smem_u32(smem);
    const int tid = threadIdx.x;
    const int lane = tid & 31, wm = tid >> 5;
    const int cta = blockIdx.x;

    const int nj = (cta < 128) ? 11 : 10;
    int j = (cta < 128) ? cta * 11 : 128 * 11 + (cta - 128) * 10;

    auto src = [&](int img) -> const char* {
        const __half* p;
        if (l0) p = g_xp + ((size_t)(img & 7) * PTOT + FRONT) * Cc;
        else    p = g_act[ps] + ((size_t)img * PTOT + FRONT) * Cc;
        return (const char*)p;
    };
    // stage full 64-ic strip (66304 B) to dst_off
    auto stage = [&](const char* s, int tb, uint32_t dst_off) {
        const char* g = s + (size_t)(tb - HALO) * 128;
        for (int i = tid; i < STRIP_PX * 8; i += NT) {
            int px = i >> 3;
            int c = (i & 7) << 4;
            uint32_t sw = (uint32_t)(px * 128 + (c ^ ((px & 7) << 4)));
            cp16(sb + dst_off + sw, g + (size_t)px * 128 + c);
        }
    };
    auto stage_w = [&](int mod) {
        const char* wsrc = (const char*)g_wH + (size_t)mod * 73728;
        for (int g = tid; g < 4608; g += NT) {
            int o = g * 16;
            int sw = o ^ ((o >> 3) & 0x70);
            cp16(sb + SW_OFF + sw, wsrc + o);
        }
    };

    // prologue: weights + A of first tile into buf0
    {
        const int img0 = j / TILES;
        const int tile0 = j - img0 * TILES;
        const int t0 = img0 >> 3;
        stage_w(layer * Mm + g_sel[t0*Ll + layer]);
        stage(src(img0), tile0 * TILE_M, SA0_OFF);
        cp_commit();
    }
    int cur_mod_t = (j / TILES) >> 3;

    for (int jj = 0; jj < nj; jj++, j++) {
        const int img = j / TILES;
        const int tile = j - img * TILES;
        const int t = img >> 3;
        const int tb = tile * TILE_M;
        const int mod = layer * Mm + g_sel[t*Ll + layer];
        const uint32_t abuf = sb + ((jj & 1) ? SA1_OFF : SA0_OFF);

        bool has_next = (jj + 1 < nj);
        int t2 = 0;
        bool mod_sw = false;
        if (has_next) {
            int j2 = j + 1;
            int img2 = j2 / TILES;
            int ntb = (j2 - img2 * TILES) * TILE_M;
            t2 = img2 >> 3;
            mod_sw = (t2 != cur_mod_t) &&
                     (g_sel[t2*Ll + layer] != g_sel[cur_mod_t*Ll + layer]);
            cp_wait<0>();
            __syncthreads();                 // A(cur) + weights ready; buf(next) free
            stage(src(img2), ntb, (jj & 1) ? SA0_OFF : SA1_OFF);
            cp_commit();
        } else {
            cp_wait<0>();
            __syncthreads();
        }

        float acc[4][8][4];
        #pragma unroll
        for (int mt = 0; mt < 4; mt++)
            #pragma unroll
            for (int nt = 0; nt < 8; nt++)
                #pragma unroll
                for (int r = 0; r < 4; r++) acc[mt][nt][r] = 0.f;

        conv_pass(acc, sb, abuf, lane, wm);

        const int g = lane >> 2, c2 = (lane & 3) * 2;
        const float* bb = enc_b + mod * 64;

        if (layer != 3) {
            __half* dst = g_act[pd] + ((size_t)img * PTOT + FRONT) * Cc;
            #pragma unroll
            for (int mt = 0; mt < 4; mt++) {
                #pragma unroll
                for (int r = 0; r < 2; r++) {
                    int row = wm * 64 + mt * 16 + g + r * 8;
                    int p = tb + row;
                    if (p < PPX) {
                        int y = p / PW, xx = p - y * PW;
                        if (y >= 1 && y <= Hh && xx >= 1 && xx <= Ww) {
                            size_t base = (size_t)p * Cc;
                            #pragma unroll
                            for (int nt = 0; nt < 8; nt++) {
                                int oc = nt * 8 + c2;
                                float f0 = fmaxf(acc[mt][nt][r*2+0] + __ldg(bb + oc),     0.f);
                                float f1 = fmaxf(acc[mt][nt][r*2+1] + __ldg(bb + oc + 1), 0.f);
                                __half2 h = __floats2half2_rn(f0, f1);
                                *(uint32_t*)(dst + base + oc) = *reinterpret_cast<uint32_t*>(&h);
                            }
                        }
                    }
                }
            }
        } else {
            // fused decoder: full 64-oc dot in-warp (sum over nt, shfl over quad)
            float wd[3][16];
            #pragma unroll
            for (int kk = 0; kk < 3; kk++)
                #pragma unroll
                for (int q = 0; q < 16; q++) {
                    int oc = (q >> 1) * 8 + c2 + (q & 1);
                    wd[kk][q] = __ldg(dec_w + ((size_t)t * 3 + kk) * 64 + oc);
                }
            #pragma unroll
            for (int mt = 0; mt < 4; mt++) {
                #pragma unroll
                for (int r = 0; r < 2; r++) {
                    float p0 = 0.f, p1 = 0.f, p2 = 0.f;
                    #pragma unroll
                    for (int nt = 0; nt < 8; nt++) {
                        int oc = nt * 8 + c2;
                        float f0 = fmaxf(acc[mt][nt][r*2+0] + __ldg(bb + oc),     0.f);
                        float f1 = fmaxf(acc[mt][nt][r*2+1] + __ldg(bb + oc + 1), 0.f);
                        p0 = fmaf(f0, wd[0][nt*2+0], fmaf(f1, wd[0][nt*2+1], p0));
                        p1 = fmaf(f0, wd[1][nt*2+0], fmaf(f1, wd[1][nt*2+1], p1));
                        p2 = fmaf(f0, wd[2][nt*2+0], fmaf(f1, wd[2][nt*2+1], p2));
                    }
                    #pragma unroll
                    for (int off = 1; off < 4; off <<= 1) {
                        p0 += __shfl_xor_sync(0xffffffffu, p0, off);
                        p1 += __shfl_xor_sync(0xffffffffu, p1, off);
                        p2 += __shfl_xor_sync(0xffffffffu, p2, off);
                    }
                    if ((lane & 3) == 0) {
                        int p = tb + wm * 64 + mt * 16 + r * 8 + g;
                        if (p < PPX) {
                            int y = p / PW, xx = p - y * PW;
                            if (y >= 1 && y <= Hh && xx >= 1 && xx <= Ww) {
                                float a0 = p0 + __ldg(dec_b + t*3 + 0);
                                float a1 = p1 + __ldg(dec_b + t*3 + 1);
                                float a2 = p2 + __ldg(dec_b + t*3 + 2);
                                if (t == 2) {
                                    float n = rsqrtf(a0*a0 + a1*a1 + a2*a2);
                                    a0 *= n; a1 *= n; a2 *= n;
                                }
                                float* op = out + ((size_t)img * 3) * HWp + (y - 1) * Ww + (xx - 1);
                                op[0] = a0;
                                op[HWp] = a1;
                                op[2*HWp] = a2;
                            }
                        }
                    }
                }
            }
        }

        // module switch: re-stage weights after all warps done with old ones
        if (has_next && mod_sw) {
            __syncthreads();
            stage_w(layer * Mm + g_sel[t2*Ll + layer]);
            cp_commit();
        }
        if (has_next) cur_mod_t = t2;
    }
}

extern "C" void kernel_launch(void* const* d_in, const int* in_sizes, int n_in,
                              void* d_out, int out_size) {
    const float* x      = (const float*)d_in[0];
    const float* alpha0 = (const float*)d_in[1];
    const float* alphas = (const float*)d_in[2];
    const float* g0     = (const float*)d_in[3];
    const float* gs     = (const float*)d_in[4];
    const float* enc_w  = (const float*)d_in[5];
    const float* enc_b  = (const float*)d_in[6];
    const float* dec_w  = (const float*)d_in[7];
    const float* dec_b  = (const float*)d_in[8];
    float* out = (float*)d_out;

    cudaFuncSetAttribute(conv_hmma, cudaFuncAttributeMaxDynamicSharedMemorySize, SMEM_TOT);

    prep_kernel<<<2110, 256>>>(x, alpha0, alphas, g0, gs, enc_w);

    conv_hmma<<<CTAS, NT, SMEM_TOT>>>(0, 1, 0, 0, enc_b, dec_w, dec_b, out);
    conv_hmma<<<CTAS, NT, SMEM_TOT>>>(1, 0, 0, 1, enc_b, dec_w, dec_b, out);
    conv_hmma<<<CTAS, NT, SMEM_TOT>>>(2, 0, 1, 0, enc_b, dec_w, dec_b, out);
    conv_hmma<<<CTAS, NT, SMEM_TOT>>>(3, 0, 0, 1, enc_b, dec_w, dec_b, out);
}

// round 12
// speedup vs baseline: 1.0314x; 1.0314x over previous
#include <cuda_runtime.h>
#include <cuda_fp16.h>
#include <cstdint>

#define Tt 3
#define Ll 4
#define Mm 3
#define Bb 8
#define Cc 64
#define Hh 128
#define Ww 128
#define HWp (Hh*Ww)
#define PW 130
#define PPX (PW*PW)              // 16900 padded pixels
#define FRONT 256
#define SLACK 384
#define PTOT (FRONT + PPX + SLACK)

#define TILE_M 256
#define HALO 131                 // PW + 1
#define STRIP_PX (TILE_M + 2*HALO)   // 518
#define STRIP_B (STRIP_PX*128)       // 66304 bytes
#define TILES 67                 // ceil(PPX/TILE_M)
#define CTAS 148
#define JOBS (Tt*Bb*TILES)       // 1608 tiles per layer

// ---- layer-3 (full-N) kernel smem ----
#define SW_OFF 0                 // weights: 9 taps x 8192 B = 73728
#define SA0_OFF 73728            // A buffer 0: 66304 B
#define SA1_OFF (SA0_OFF + STRIP_B)  // 140032
#define SMEM_TOT (SA1_OFF + STRIP_B + 128) // 206464

// ---- layers 0-2 (half-N, 2 CTA/SM) kernel smem ----
#define CTAS2 296
#define JOBS2 (2*JOBS)           // 3216
#define SA2_OFF 36864            // weights: 9 taps x 4096 B = 36864
#define SMEM2_TOT (SA2_OFF + STRIP_B + 128)  // 103296

// ---------------- device state ----------------
__device__ int g_sel[Tt*Ll];
// weights fp16: [mod 12][tap 9][oc 64][ic 64]
__device__ __align__(256) __half g_wH[(size_t)12*9*64*64];
// layer-0 input, padded NHWC fp16: [b][PTOT][64]
__device__ __align__(256) __half g_xp[(size_t)Bb*PTOT*Cc];
// ping-pong activations: [pp 2][t*b 24][PTOT][64]
__device__ __align__(256) __half g_act[2][(size_t)Tt*Bb*PTOT*Cc];

// ---------------- helpers ----------------
__device__ __forceinline__ uint32_t smem_u32(const void* p) {
    uint32_t a;
    asm("{ .reg .u64 t; cvta.to.shared.u64 t, %1; cvt.u32.u64 %0, t; }" : "=r"(a) : "l"(p));
    return a;
}
__device__ __forceinline__ void cp16(uint32_t sdst, const void* gsrc) {
    asm volatile("cp.async.cg.shared.global [%0], [%1], 16;" :: "r"(sdst), "l"(gsrc) : "memory");
}
__device__ __forceinline__ void cp_commit() { asm volatile("cp.async.commit_group;" ::: "memory"); }
template <int N>
__device__ __forceinline__ void cp_wait() {
    asm volatile("cp.async.wait_group %0;" :: "n"(N) : "memory");
}

__device__ __forceinline__ void ldmx4(uint32_t* r, uint32_t addr) {
    asm volatile("ldmatrix.sync.aligned.m8n8.x4.shared.b16 {%0,%1,%2,%3}, [%4];"
                 : "=r"(r[0]), "=r"(r[1]), "=r"(r[2]), "=r"(r[3]) : "r"(addr));
}
__device__ __forceinline__ void mma16816(float* c, const uint32_t* a, const uint32_t* b) {
    asm volatile("mma.sync.aligned.m16n8k16.row.col.f32.f16.f16.f32 "
                 "{%0,%1,%2,%3}, {%4,%5,%6,%7}, {%8,%9}, {%0,%1,%2,%3};"
                 : "+f"(c[0]), "+f"(c[1]), "+f"(c[2]), "+f"(c[3])
                 : "r"(a[0]), "r"(a[1]), "r"(a[2]), "r"(a[3]), "r"(b[0]), "r"(b[1]));
}

// ---------------- fused prep kernel ----------------------------------------
__global__ void __launch_bounds__(256) prep_kernel(
    const float* __restrict__ x, const float* __restrict__ alpha0,
    const float* __restrict__ alphas, const float* __restrict__ g0,
    const float* __restrict__ gs, const float* __restrict__ enc_w)
{
    const int bid = blockIdx.x;
    const int tid = threadIdx.x;

    if (bid < 128) {
        // ---- xprep: NCHW fp32 -> padded NHWC fp16, 4 px per thread ----
        int idx = bid * 256 + tid;            // [0, 32768)
        int b = idx >> 12;
        int pg = idx & 4095;
        int px0 = pg * 4;
        int y = px0 >> 7, x0 = px0 & 127;
        int p0 = (y + 1) * PW + (x0 + 1);
        const float* xs = x + ((size_t)b * Cc << 14) + px0;
        __half* dh = g_xp + ((size_t)b * PTOT + FRONT + p0) * Cc;
        #pragma unroll
        for (int g = 0; g < 8; g++) {
            float4 v[8];
            #pragma unroll
            for (int j = 0; j < 8; j++)
                v[j] = *reinterpret_cast<const float4*>(xs + (size_t)(g*8 + j) * HWp);
            #pragma unroll
            for (int e = 0; e < 4; e++) {
                uint32_t hv[4];
                #pragma unroll
                for (int q = 0; q < 4; q++) {
                    __half2 h = __floats2half2_rn((&v[q*2].x)[e], (&v[q*2+1].x)[e]);
                    hv[q] = *reinterpret_cast<uint32_t*>(&h);
                }
                *reinterpret_cast<uint4*>(dh + (size_t)e * Cc + g*8) =
                    make_uint4(hv[0], hv[1], hv[2], hv[3]);
            }
        }
    } else if (bid < 1856) {
        // ---- wprep: OIHW fp32 -> [mod][tap][oc][ic] fp16 ----
        int i = (bid - 128) * 256 + tid;       // [0, 442368)
        int ic  = i & 63;
        int oc  = (i >> 6) & 63;
        int tap = (i >> 12) % 9;
        int mod = i / 36864;
        float w = enc_w[(((size_t)(mod*Cc + oc))*Cc + ic)*9 + tap];
        g_wH[(((size_t)mod*9 + tap)*64 + oc)*64 + ic] = __float2half_rn(w);
    } else if (bid < 2109) {
        // ---- zero border pixels of 56 padded planes (8 xp + 48 act) ----
        int item = (bid - 1856) * 256 + tid;
        if (item >= 56 * 1156) return;
        int plane = item / 1156;
        int bi = item - plane * 1156;
        int px;
        if (bi < 256) px = bi;
        else {
            bi -= 256;
            if (bi < 130) px = FRONT + bi;
            else {
                bi -= 130;
                if (bi < 256) { int r = bi >> 1, c = bi & 1; px = FRONT + (r+1)*PW + c*129; }
                else {
                    bi -= 256;
                    if (bi < 130) px = FRONT + 129*PW + bi;
                    else px = FRONT + PPX + (bi - 130);
                }
            }
        }
        __half* base;
        if (plane < 8) base = g_xp + (size_t)plane * PTOT * Cc;
        else {
            int k = plane - 8;
            base = g_act[k / 24] + (size_t)(k % 24) * PTOT * Cc;
        }
        uint4 z = make_uint4(0, 0, 0, 0);
        uint4* d = (uint4*)(base + (size_t)px * Cc);
        #pragma unroll
        for (int q = 0; q < 8; q++) d[q] = z;
    } else {
        // ---- routing ----
        int t = tid;
        if (t >= Tt) return;
        int idx = 0;
        {
            float best = -1e30f; int bi2 = 0;
            #pragma unroll
            for (int m = 0; m < Mm; m++) {
                float v = alpha0[t*Mm + m] + g0[t*Mm + m];
                if (v > best) { best = v; bi2 = m; }
            }
            idx = bi2; g_sel[t*Ll + 0] = bi2;
        }
        for (int l = 1; l < Ll; l++) {
            const float* a = alphas + ((((size_t)(l-1)*Tt + t)*Mm + idx)*Mm);
            const float* g = gs     + ((((size_t)(l-1)*Tt + t)*Mm + idx)*Mm);
            float best = -1e30f; int bi2 = 0;
            #pragma unroll
            for (int m = 0; m < Mm; m++) {
                float v = a[m] + g[m];
                if (v > best) { best = v; bi2 = m; }
            }
            idx = bi2; g_sel[t*Ll + l] = bi2;
        }
    }
}

// ============================================================================
// Layers 0-2: half-N kernel, 4 warps, 2 CTAs/SM (occupancy hides bubbles)
// ============================================================================
__device__ __forceinline__ void conv_pass2(float (*acc)[4][4], uint32_t sb,
                                           int lane, int wm) {
    const int arow = lane & 15;
    const int akhalf = (lane >> 4) << 4;
    const int ocl = (lane & 7) + ((lane >> 4) << 3);
    const int bkhalf = ((lane >> 3) & 1) << 4;

    int obase[2], oxor[2];
    #pragma unroll
    for (int pr = 0; pr < 2; pr++) {
        int oc = pr * 16 + ocl;                 // local oc within 32-row slice
        obase[pr] = oc * 128;
        oxor[pr] = (oc & 7) << 4;
    }

    #pragma unroll
    for (int tap = 0; tap < 9; tap++) {
        const int dy = tap / 3 - 1, dx = tap % 3 - 1;
        const int pxoff = HALO + dy * PW + dx;
        const uint32_t bb = sb + tap * 4096;

        int abase[4], axor[4];
        #pragma unroll
        for (int mt = 0; mt < 4; mt++) {
            int px = wm * 64 + mt * 16 + arow + pxoff;
            abase[mt] = px * 128;
            axor[mt] = (px & 7) << 4;
        }

        #pragma unroll
        for (int k = 0; k < 4; k++) {
            uint32_t bh[4][2];
            #pragma unroll
            for (int pr = 0; pr < 2; pr++) {
                uint32_t off = obase[pr] + (uint32_t)((k * 32 + bkhalf) ^ oxor[pr]);
                uint32_t r[4];
                ldmx4(r, bb + off);
                bh[pr*2][0] = r[0]; bh[pr*2][1] = r[1];
                bh[pr*2+1][0] = r[2]; bh[pr*2+1][1] = r[3];
            }
            uint32_t aF[4][4];
            #pragma unroll
            for (int mt = 0; mt < 4; mt++) {
                uint32_t off = abase[mt] + (uint32_t)((k * 32 + akhalf) ^ axor[mt]);
                ldmx4(aF[mt], sb + SA2_OFF + off);
            }
            #pragma unroll
            for (int mt = 0; mt < 4; mt++)
                #pragma unroll
                for (int nt = 0; nt < 4; nt++)
                    mma16816(acc[mt][nt], aF[mt], bh[nt]);
        }
    }
}

__global__ void __launch_bounds__(128, 2) conv_hmma2(
    int layer, int l0, int ps, int pd, const float* __restrict__ enc_b)
{
    extern __shared__ __align__(1024) char smem[];
    const uint32_t sb = smem_u32(smem);
    const int tid = threadIdx.x;
    const int lane = tid & 31, wm = tid >> 5;
    const int cta = blockIdx.x;

    // JOBS2 = 3216 over 296 CTAs: 256 x 11 + 40 x 10
    const int nj = (cta < 256) ? 11 : 10;
    int j = (cta < 256) ? cta * 11 : 2816 + (cta - 256) * 10;

    auto src = [&](int img) -> const char* {
        const __half* p;
        if (l0) p = g_xp + ((size_t)(img & 7) * PTOT + FRONT) * Cc;
        else    p = g_act[ps] + ((size_t)img * PTOT + FRONT) * Cc;
        return (const char*)p;
    };
    auto stageA = [&](const char* s, int tb) {
        const char* g = s + (size_t)(tb - HALO) * 128;
        for (int i = tid; i < STRIP_PX * 8; i += 128) {
            int px = i >> 3;
            int c = (i & 7) << 4;
            uint32_t sw = (uint32_t)(px * 128 + (c ^ ((px & 7) << 4)));
            cp16(sb + SA2_OFF + sw, g + (size_t)px * 128 + c);
        }
    };
    auto stage_w = [&](int mod, int half) {
        const char* wsrc = (const char*)g_wH + (size_t)mod * 73728 + half * 4096;
        for (int g = tid; g < 2304; g += 128) {
            int tap = g >> 8;
            int o = (g & 255) * 16;
            int sw = o ^ ((o >> 3) & 0x70);
            cp16(sb + tap * 4096 + sw, wsrc + (size_t)tap * 8192 + o);
        }
    };
    auto jdec = [&](int jx, int& half, int& img, int& tb, int& mod) {
        half = (jx >= JOBS) ? 1 : 0;
        int tj = jx - half * JOBS;
        img = tj / TILES;
        tb = (tj - img * TILES) * TILE_M;
        mod = layer * Mm + g_sel[(img >> 3) * Ll + layer];
    };

    // prologue
    int half, img, tb, mod;
    jdec(j, half, img, tb, mod);
    stage_w(mod, half);
    stageA(src(img), tb);
    cp_commit();
    int cur_key = mod * 2 + half;

    for (int jj = 0; jj < nj; jj++, j++) {
        jdec(j, half, img, tb, mod);

        cp_wait<0>();
        __syncthreads();                 // A + W ready

        float acc[4][4][4];
        #pragma unroll
        for (int mt = 0; mt < 4; mt++)
            #pragma unroll
            for (int nt = 0; nt < 4; nt++)
                #pragma unroll
                for (int r = 0; r < 4; r++) acc[mt][nt][r] = 0.f;

        conv_pass2(acc, sb, lane, wm);

        __syncthreads();                 // all warps done reading A + W

        if (jj + 1 < nj) {
            int h2, img2, tb2, mod2;
            jdec(j + 1, h2, img2, tb2, mod2);
            stageA(src(img2), tb2);
            int key2 = mod2 * 2 + h2;
            if (key2 != cur_key) { stage_w(mod2, h2); cur_key = key2; }
            cp_commit();
        }

        // epilogue: bias + relu + fp16 store of this CTA's 32 ocs
        const int g = lane >> 2, c2 = (lane & 3) * 2;
        const float* bb = enc_b + mod * 64 + half * 32;
        __half* dst = g_act[pd] + ((size_t)img * PTOT + FRONT) * Cc + half * 32;
        #pragma unroll
        for (int mt = 0; mt < 4; mt++) {
            #pragma unroll
            for (int r = 0; r < 2; r++) {
                int row = wm * 64 + mt * 16 + g + r * 8;
                int p = tb + row;
                if (p < PPX) {
                    int y = p / PW, xx = p - y * PW;
                    if (y >= 1 && y <= Hh && xx >= 1 && xx <= Ww) {
                        size_t base = (size_t)p * Cc;
                        #pragma unroll
                        for (int nt = 0; nt < 4; nt++) {
                            int oc = nt * 8 + c2;
                            float f0 = fmaxf(acc[mt][nt][r*2+0] + __ldg(bb + oc),     0.f);
                            float f1 = fmaxf(acc[mt][nt][r*2+1] + __ldg(bb + oc + 1), 0.f);
                            __half2 h = __floats2half2_rn(f0, f1);
                            *(uint32_t*)(dst + base + oc) = *reinterpret_cast<uint32_t*>(&h);
                        }
                    }
                }
            }
        }
    }
}

// ============================================================================
// Layer 3: full-N kernel with fused decoder (proven R10 config)
// ============================================================================
__device__ __forceinline__ void conv_pass(float (*acc)[4][4], uint32_t sb,
                                          uint32_t abuf, int lane, int wm, int wn) {
    const int arow = lane & 15;
    const int akhalf = (lane >> 4) << 4;
    const int ocl = (lane & 7) + ((lane >> 4) << 3);
    const int bkhalf = ((lane >> 3) & 1) << 4;

    int obase[2], oxor[2];
    #pragma unroll
    for (int pr = 0; pr < 2; pr++) {
        int oc = wn * 32 + pr * 16 + ocl;
        obase[pr] = oc * 128;
        oxor[pr] = (oc & 7) << 4;
    }

    #pragma unroll
    for (int tap = 0; tap < 9; tap++) {
        const int dy = tap / 3 - 1, dx = tap % 3 - 1;
        const int pxoff = HALO + dy * PW + dx;
        const uint32_t bb = sb + SW_OFF + tap * 8192;

        int abase[4], axor[4];
        #pragma unroll
        for (int mt = 0; mt < 4; mt++) {
            int px = wm * 64 + mt * 16 + arow + pxoff;
            abase[mt] = px * 128;
            axor[mt] = (px & 7) << 4;
        }

        #pragma unroll
        for (int k = 0; k < 4; k++) {
            uint32_t bh[4][2];
            #pragma unroll
            for (int pr = 0; pr < 2; pr++) {
                uint32_t off = obase[pr] + (uint32_t)((k * 32 + bkhalf) ^ oxor[pr]);
                uint32_t r[4];
                ldmx4(r, bb + off);
                bh[pr*2][0] = r[0]; bh[pr*2][1] = r[1];
                bh[pr*2+1][0] = r[2]; bh[pr*2+1][1] = r[3];
            }
            uint32_t aF[4][4];
            #pragma unroll
            for (int mt = 0; mt < 4; mt++) {
                uint32_t off = abase[mt] + (uint32_t)((k * 32 + akhalf) ^ axor[mt]);
                ldmx4(aF[mt], abuf + off);
            }
            #pragma unroll
            for (int mt = 0; mt < 4; mt++)
                #pragma unroll
                for (int nt = 0; nt < 4; nt++)
                    mma16816(acc[mt][nt], aF[mt], bh[nt]);
        }
    }
}

__global__ void __launch_bounds__(256) conv_hmma(
    int layer, int l0, int ps, int pd,
    const float* __restrict__ enc_b,
    const float* __restrict__ dec_w, const float* __restrict__ dec_b,
    float* __restrict__ out)
{
    extern __shared__ __align__(1024) char smem[];
    const uint32_t sb = smem_u32(smem);
    const int tid = threadIdx.x;
    const int lane = tid & 31, wid = tid >> 5;
    const int wm = wid >> 1, wn = wid & 1;
    const int cta = blockIdx.x;

    const int nj = (cta < 128) ? 11 : 10;
    int j = (cta < 128) ? cta * 11 : 128 * 11 + (cta - 128) * 10;

    auto src = [&](int img) -> const char* {
        const __half* p;
        if (l0) p = g_xp + ((size_t)(img & 7) * PTOT + FRONT) * Cc;
        else    p = g_act[ps] + ((size_t)img * PTOT + FRONT) * Cc;
        return (const char*)p;
    };
    auto stage = [&](const char* s, int tb, uint32_t dst_off) {
        const char* g = s + (size_t)(tb - HALO) * 128;
        for (int i = tid; i < STRIP_PX * 8; i += 256) {
            int px = i >> 3;
            int c = (i & 7) << 4;
            uint32_t sw = (uint32_t)(px * 128 + (c ^ ((px & 7) << 4)));
            cp16(sb + dst_off + sw, g + (size_t)px * 128 + c);
        }
    };
    auto stage_w = [&](int mod) {
        const char* wsrc = (const char*)g_wH + (size_t)mod * 73728;
        for (int g = tid; g < 4608; g += 256) {
            int o = g * 16;
            int sw = o ^ ((o >> 3) & 0x70);
            cp16(sb + SW_OFF + sw, wsrc + o);
        }
    };

    {
        const int img0 = j / TILES;
        const int tile0 = j - img0 * TILES;
        const int t0 = img0 >> 3;
        stage_w(layer * Mm + g_sel[t0*Ll + layer]);
        stage(src(img0), tile0 * TILE_M, SA0_OFF);
        cp_commit();
    }
    int cur_mod_t = (j / TILES) >> 3;

    for (int jj = 0; jj < nj; jj++, j++) {
        const int img = j / TILES;
        const int tile = j - img * TILES;
        const int t = img >> 3;
        const int tb = tile * TILE_M;
        const int mod = layer * Mm + g_sel[t*Ll + layer];
        const uint32_t abuf = sb + ((jj & 1) ? SA1_OFF : SA0_OFF);

        bool has_next = (jj + 1 < nj);
        int t2 = 0;
        bool mod_sw = false;
        if (has_next) {
            int j2 = j + 1;
            int img2 = j2 / TILES;
            int ntb = (j2 - img2 * TILES) * TILE_M;
            t2 = img2 >> 3;
            mod_sw = (t2 != cur_mod_t) &&
                     (g_sel[t2*Ll + layer] != g_sel[cur_mod_t*Ll + layer]);
            cp_wait<0>();
            __syncthreads();
            stage(src(img2), ntb, (jj & 1) ? SA0_OFF : SA1_OFF);
            cp_commit();
        } else {
            cp_wait<0>();
            __syncthreads();
        }

        float acc[4][4][4];
        #pragma unroll
        for (int mt = 0; mt < 4; mt++)
            #pragma unroll
            for (int nt = 0; nt < 4; nt++)
                #pragma unroll
                for (int r = 0; r < 4; r++) acc[mt][nt][r] = 0.f;

        conv_pass(acc, sb, abuf, lane, wm, wn);

        const int g = lane >> 2, c2 = (lane & 3) * 2;
        const float* bb = enc_b + mod * 64;

        if (layer != 3) {
            __half* dst = g_act[pd] + ((size_t)img * PTOT + FRONT) * Cc;
            #pragma unroll
            for (int mt = 0; mt < 4; mt++) {
                #pragma unroll
                for (int r = 0; r < 2; r++) {
                    int row = wm * 64 + mt * 16 + g + r * 8;
                    int p = tb + row;
                    if (p < PPX) {
                        int y = p / PW, xx = p - y * PW;
                        if (y >= 1 && y <= Hh && xx >= 1 && xx <= Ww) {
                            size_t base = (size_t)p * Cc;
                            #pragma unroll
                            for (int nt = 0; nt < 4; nt++) {
                                int oc = wn * 32 + nt * 8 + c2;
                                float f0 = fmaxf(acc[mt][nt][r*2+0] + __ldg(bb + oc),     0.f);
                                float f1 = fmaxf(acc[mt][nt][r*2+1] + __ldg(bb + oc + 1), 0.f);
                                __half2 h = __floats2half2_rn(f0, f1);
                                *(uint32_t*)(dst + base + oc) = *reinterpret_cast<uint32_t*>(&h);
                            }
                        }
                    }
                }
            }
        } else {
            // fused decoder (uses smem scratch above SA1 region is free now? No —
            // use a small static shared buffer)
            __shared__ float dbuf[TILE_M][2][3];
            float wd[3][8];
            #pragma unroll
            for (int kk = 0; kk < 3; kk++)
                #pragma unroll
                for (int q = 0; q < 8; q++) {
                    int oc = wn * 32 + (q >> 1) * 8 + c2 + (q & 1);
                    wd[kk][q] = __ldg(dec_w + ((size_t)t * 3 + kk) * 64 + oc);
                }
            #pragma unroll
            for (int mt = 0; mt < 4; mt++) {
                #pragma unroll
                for (int r = 0; r < 2; r++) {
                    float p0 = 0.f, p1 = 0.f, p2 = 0.f;
                    #pragma unroll
                    for (int nt = 0; nt < 4; nt++) {
                        int oc = wn * 32 + nt * 8 + c2;
                        float f0 = fmaxf(acc[mt][nt][r*2+0] + __ldg(bb + oc),     0.f);
                        float f1 = fmaxf(acc[mt][nt][r*2+1] + __ldg(bb + oc + 1), 0.f);
                        p0 = fmaf(f0, wd[0][nt*2+0], fmaf(f1, wd[0][nt*2+1], p0));
                        p1 = fmaf(f0, wd[1][nt*2+0], fmaf(f1, wd[1][nt*2+1], p1));
                        p2 = fmaf(f0, wd[2][nt*2+0], fmaf(f1, wd[2][nt*2+1], p2));
                    }
                    #pragma unroll
                    for (int off = 1; off < 4; off <<= 1) {
                        p0 += __shfl_xor_sync(0xffffffffu, p0, off);
                        p1 += __shfl_xor_sync(0xffffffffu, p1, off);
                        p2 += __shfl_xor_sync(0xffffffffu, p2, off);
                    }
                    if ((lane & 3) == 0) {
                        int pix = wm * 64 + mt * 16 + r * 8 + g;
                        dbuf[pix][wn][0] = p0;
                        dbuf[pix][wn][1] = p1;
                        dbuf[pix][wn][2] = p2;
                    }
                }
            }
            __syncthreads();
            {
                int p = tb + tid;
                if (p < PPX) {
                    int y = p / PW, xx = p - y * PW;
                    if (y >= 1 && y <= Hh && xx >= 1 && xx <= Ww) {
                        float a0 = dbuf[tid][0][0] + dbuf[tid][1][0] + __ldg(dec_b + t*3 + 0);
                        float a1 = dbuf[tid][0][1] + dbuf[tid][1][1] + __ldg(dec_b + t*3 + 1);
                        float a2 = dbuf[tid][0][2] + dbuf[tid][1][2] + __ldg(dec_b + t*3 + 2);
                        if (t == 2) {
                            float n = rsqrtf(a0*a0 + a1*a1 + a2*a2);
                            a0 *= n; a1 *= n; a2 *= n;
                        }
                        float* op = out + ((size_t)img * 3) * HWp + (y - 1) * Ww + (xx - 1);
                        op[0] = a0;
                        op[HWp] = a1;
                        op[2*HWp] = a2;
                    }
                }
            }
        }

        if (has_next && mod_sw) {
            __syncthreads();
            stage_w(layer * Mm + g_sel[t2*Ll + layer]);
            cp_commit();
        }
        if (has_next) cur_mod_t = t2;
    }
}

extern "C" void kernel_launch(void* const* d_in, const int* in_sizes, int n_in,
                              void* d_out, int out_size) {
    const float* x      = (const float*)d_in[0];
    const float* alpha0 = (const float*)d_in[1];
    const float* alphas = (const float*)d_in[2];
    const float* g0     = (const float*)d_in[3];
    const float* gs     = (const float*)d_in[4];
    const float* enc_w  = (const float*)d_in[5];
    const float* enc_b  = (const float*)d_in[6];
    const float* dec_w  = (const float*)d_in[7];
    const float* dec_b  = (const float*)d_in[8];
    float* out = (float*)d_out;

    cudaFuncSetAttribute(conv_hmma, cudaFuncAttributeMaxDynamicSharedMemorySize, SMEM_TOT);
    cudaFuncSetAttribute(conv_hmma2, cudaFuncAttributeMaxDynamicSharedMemorySize, SMEM2_TOT);

    prep_kernel<<<2110, 256>>>(x, alpha0, alphas, g0, gs, enc_w);

    conv_hmma2<<<CTAS2, 128, SMEM2_TOT>>>(0, 1, 0, 0, enc_b);
    conv_hmma2<<<CTAS2, 128, SMEM2_TOT>>>(1, 0, 0, 1, enc_b);
    conv_hmma2<<<CTAS2, 128, SMEM2_TOT>>>(2, 0, 1, 0, enc_b);
    conv_hmma<<<CTAS, 256, SMEM_TOT>>>(3, 0, 0, 1, enc_b, dec_w, dec_b, out);
}

// round 13
// speedup vs baseline: 1.0501x; 1.0182x over previous
#include <cuda_runtime.h>
#include <cuda_fp16.h>
#include <cstdint>

#define Tt 3
#define Ll 4
#define Mm 3
#define Bb 8
#define Cc 64
#define Hh 128
#define Ww 128
#define HWp (Hh*Ww)
#define PW 130
#define PPX (PW*PW)              // 16900 padded pixels
#define FRONT 256
#define SLACK 384
#define PTOT (FRONT + PPX + SLACK)

#define TILE_M 256
#define HALO 131                 // PW + 1
#define STRIP_PX (TILE_M + 2*HALO)   // 518
#define STRIP_B (STRIP_PX*128)       // 66304 bytes
#define TILES 67                 // ceil(PPX/TILE_M)
#define CTAS 148
#define JOBS (Tt*Bb*TILES)       // 1608 tiles per layer

#define SW_OFF 0                 // weights: 9 taps x 8192 B = 73728
#define SA0_OFF 73728            // A buffer 0: 66304 B
#define SA1_OFF (SA0_OFF + STRIP_B)  // 140032
#define SMEM_TOT (SA1_OFF + STRIP_B + 128) // 206464

// ---------------- device state ----------------
__device__ int g_sel[Tt*Ll];
// weights fp16: [mod 12][tap 9][oc 64][ic 64]
__device__ __align__(256) __half g_wH[(size_t)12*9*64*64];
// layer-0 input, padded NHWC fp16: [b][PTOT][64]
__device__ __align__(256) __half g_xp[(size_t)Bb*PTOT*Cc];
// ping-pong activations: [pp 2][t*b 24][PTOT][64]
__device__ __align__(256) __half g_act[2][(size_t)Tt*Bb*PTOT*Cc];

// ---------------- helpers ----------------
__device__ __forceinline__ uint32_t smem_u32(const void* p) {
    uint32_t a;
    asm("{ .reg .u64 t; cvta.to.shared.u64 t, %1; cvt.u32.u64 %0, t; }" : "=r"(a) : "l"(p));
    return a;
}
__device__ __forceinline__ void cp16(uint32_t sdst, const void* gsrc) {
    asm volatile("cp.async.cg.shared.global [%0], [%1], 16;" :: "r"(sdst), "l"(gsrc) : "memory");
}
__device__ __forceinline__ void cp_commit() { asm volatile("cp.async.commit_group;" ::: "memory"); }
template <int N>
__device__ __forceinline__ void cp_wait() {
    asm volatile("cp.async.wait_group %0;" :: "n"(N) : "memory");
}

__device__ __forceinline__ void ldmx4(uint32_t* r, uint32_t addr) {
    asm volatile("ldmatrix.sync.aligned.m8n8.x4.shared.b16 {%0,%1,%2,%3}, [%4];"
                 : "=r"(r[0]), "=r"(r[1]), "=r"(r[2]), "=r"(r[3]) : "r"(addr));
}
__device__ __forceinline__ void mma16816(float* c, const uint32_t* a, const uint32_t* b) {
    asm volatile("mma.sync.aligned.m16n8k16.row.col.f32.f16.f16.f32 "
                 "{%0,%1,%2,%3}, {%4,%5,%6,%7}, {%8,%9}, {%0,%1,%2,%3};"
                 : "+f"(c[0]), "+f"(c[1]), "+f"(c[2]), "+f"(c[3])
                 : "r"(a[0]), "r"(a[1]), "r"(a[2]), "r"(a[3]), "r"(b[0]), "r"(b[1]));
}

// ---------------- fused prep kernel ----------------------------------------
__global__ void __launch_bounds__(256) prep_kernel(
    const float* __restrict__ x, const float* __restrict__ alpha0,
    const float* __restrict__ alphas, const float* __restrict__ g0,
    const float* __restrict__ gs, const float* __restrict__ enc_w)
{
    const int bid = blockIdx.x;
    const int tid = threadIdx.x;

    if (bid < 128) {
        // ---- xprep: NCHW fp32 -> padded NHWC fp16, 4 px per thread ----
        int idx = bid * 256 + tid;            // [0, 32768)
        int b = idx >> 12;
        int pg = idx & 4095;
        int px0 = pg * 4;
        int y = px0 >> 7, x0 = px0 & 127;
        int p0 = (y + 1) * PW + (x0 + 1);
        const float* xs = x + ((size_t)b * Cc << 14) + px0;
        __half* dh = g_xp + ((size_t)b * PTOT + FRONT + p0) * Cc;
        #pragma unroll
        for (int g = 0; g < 8; g++) {
            float4 v[8];
            #pragma unroll
            for (int j = 0; j < 8; j++)
                v[j] = *reinterpret_cast<const float4*>(xs + (size_t)(g*8 + j) * HWp);
            #pragma unroll
            for (int e = 0; e < 4; e++) {
                uint32_t hv[4];
                #pragma unroll
                for (int q = 0; q < 4; q++) {
                    __half2 h = __floats2half2_rn((&v[q*2].x)[e], (&v[q*2+1].x)[e]);
                    hv[q] = *reinterpret_cast<uint32_t*>(&h);
                }
                *reinterpret_cast<uint4*>(dh + (size_t)e * Cc + g*8) =
                    make_uint4(hv[0], hv[1], hv[2], hv[3]);
            }
        }
    } else if (bid < 1856) {
        // ---- wprep: OIHW fp32 -> [mod][tap][oc][ic] fp16 ----
        int i = (bid - 128) * 256 + tid;       // [0, 442368)
        int ic  = i & 63;
        int oc  = (i >> 6) & 63;
        int tap = (i >> 12) % 9;
        int mod = i / 36864;
        float w = enc_w[(((size_t)(mod*Cc + oc))*Cc + ic)*9 + tap];
        g_wH[(((size_t)mod*9 + tap)*64 + oc)*64 + ic] = __float2half_rn(w);
    } else if (bid < 2109) {
        // ---- zero border pixels of 56 padded planes (8 xp + 48 act) ----
        int item = (bid - 1856) * 256 + tid;
        if (item >= 56 * 1156) return;
        int plane = item / 1156;
        int bi = item - plane * 1156;
        int px;
        if (bi < 256) px = bi;
        else {
            bi -= 256;
            if (bi < 130) px = FRONT + bi;
            else {
                bi -= 130;
                if (bi < 256) { int r = bi >> 1, c = bi & 1; px = FRONT + (r+1)*PW + c*129; }
                else {
                    bi -= 256;
                    if (bi < 130) px = FRONT + 129*PW + bi;
                    else px = FRONT + PPX + (bi - 130);
                }
            }
        }
        __half* base;
        if (plane < 8) base = g_xp + (size_t)plane * PTOT * Cc;
        else {
            int k = plane - 8;
            base = g_act[k / 24] + (size_t)(k % 24) * PTOT * Cc;
        }
        uint4 z = make_uint4(0, 0, 0, 0);
        uint4* d = (uint4*)(base + (size_t)px * Cc);
        #pragma unroll
        for (int q = 0; q < 8; q++) d[q] = z;
    } else {
        // ---- routing ----
        int t = tid;
        if (t >= Tt) return;
        int idx = 0;
        {
            float best = -1e30f; int bi2 = 0;
            #pragma unroll
            for (int m = 0; m < Mm; m++) {
                float v = alpha0[t*Mm + m] + g0[t*Mm + m];
                if (v > best) { best = v; bi2 = m; }
            }
            idx = bi2; g_sel[t*Ll + 0] = bi2;
        }
        for (int l = 1; l < Ll; l++) {
            const float* a = alphas + ((((size_t)(l-1)*Tt + t)*Mm + idx)*Mm);
            const float* g = gs     + ((((size_t)(l-1)*Tt + t)*Mm + idx)*Mm);
            float best = -1e30f; int bi2 = 0;
            #pragma unroll
            for (int m = 0; m < Mm; m++) {
                float v = a[m] + g[m];
                if (v > best) { best = v; bi2 = m; }
            }
            idx = bi2; g_sel[t*Ll + l] = bi2;
        }
    }
}

// ---------------- software-pipelined conv pass ------------------------------
// 36 steps (tap*4 + k), fragments double-buffered in registers: LDSM for step
// s+1 issues BEFORE the HMMAs of step s -> tensor pipe stays fed.
__device__ __forceinline__ void conv_pass(float (*acc)[4][4], uint32_t sb,
                                          uint32_t abuf, int lane, int wm, int wn) {
    const int arow = lane & 15;
    const int akhalf = (lane >> 4) << 4;
    const int ocl = (lane & 7) + ((lane >> 4) << 3);
    const int bkhalf = ((lane >> 3) & 1) << 4;

    int obase[2], oxor[2];
    #pragma unroll
    for (int pr = 0; pr < 2; pr++) {
        int oc = wn * 32 + pr * 16 + ocl;
        obase[pr] = oc * 128;
        oxor[pr] = (oc & 7) << 4;
    }
    // per-tap A base addresses (row within strip) — precompute
    uint32_t abase[9];
    uint32_t axor[9][4];
    #pragma unroll
    for (int tap = 0; tap < 9; tap++) {
        const int dy = tap / 3 - 1, dx = tap % 3 - 1;
        const int pxoff = HALO + dy * PW + dx;
        (void)abase;
        #pragma unroll
        for (int mt = 0; mt < 4; mt++) {
            int px = wm * 64 + mt * 16 + arow + pxoff;
            axor[tap][mt] = (uint32_t)(px * 128) + (uint32_t)(akhalf ^ ((px & 7) << 4));
        }
    }

    uint32_t aF[2][4][4];
    uint32_t bF[2][4][2];

    // load step 0
    {
        #pragma unroll
        for (int pr = 0; pr < 2; pr++) {
            uint32_t off = obase[pr] + (uint32_t)(bkhalf ^ oxor[pr]);
            uint32_t r[4];
            ldmx4(r, sb + SW_OFF + off);
            bF[0][pr*2][0] = r[0]; bF[0][pr*2][1] = r[1];
            bF[0][pr*2+1][0] = r[2]; bF[0][pr*2+1][1] = r[3];
        }
        #pragma unroll
        for (int mt = 0; mt < 4; mt++)
            ldmx4(aF[0][mt], abuf + axor[0][mt]);
    }

    #pragma unroll
    for (int s = 0; s < 36; s++) {
        const int cur = s & 1, nxt = cur ^ 1;
        if (s < 35) {
            const int s2 = s + 1;
            const int tap2 = s2 >> 2, k2 = s2 & 3;
            const uint32_t bb2 = sb + SW_OFF + tap2 * 8192;
            #pragma unroll
            for (int pr = 0; pr < 2; pr++) {
                uint32_t off = obase[pr] + (uint32_t)((k2 * 32 + bkhalf) ^ oxor[pr]);
                uint32_t r[4];
                ldmx4(r, bb2 + off);
                bF[nxt][pr*2][0] = r[0]; bF[nxt][pr*2][1] = r[1];
                bF[nxt][pr*2+1][0] = r[2]; bF[nxt][pr*2+1][1] = r[3];
            }
            #pragma unroll
            for (int mt = 0; mt < 4; mt++) {
                // axor includes akhalf at k=0; xor with k2*32 shifts the k-slot
                uint32_t base = axor[tap2][mt];
                ldmx4(aF[nxt][mt], abuf + (base ^ (uint32_t)(k2 * 32)));
            }
        }
        #pragma unroll
        for (int mt = 0; mt < 4; mt++)
            #pragma unroll
            for (int nt = 0; nt < 4; nt++)
                mma16816(acc[mt][nt], aF[cur][mt], bF[cur][nt]);
    }
}

// ---------------- conv layer kernel ----------------------------------------
__global__ void __launch_bounds__(256, 1) conv_hmma(
    int layer, int l0, int ps, int pd,
    const float* __restrict__ enc_b,
    const float* __restrict__ dec_w, const float* __restrict__ dec_b,
    float* __restrict__ out)
{
    extern __shared__ __align__(1024) char smem[];
    const uint32_t sb = smem_u32(smem);
    const int tid = threadIdx.x;
    const int lane = tid & 31, wid = tid >> 5;
    const int wm = wid >> 1, wn = wid & 1;
    const int cta = blockIdx.x;

    const int nj = (cta < 128) ? 11 : 10;
    int j = (cta < 128) ? cta * 11 : 128 * 11 + (cta - 128) * 10;

    auto src = [&](int img) -> const char* {
        const __half* p;
        if (l0) p = g_xp + ((size_t)(img & 7) * PTOT + FRONT) * Cc;
        else    p = g_act[ps] + ((size_t)img * PTOT + FRONT) * Cc;
        return (const char*)p;
    };
    auto stage = [&](const char* s, int tb, uint32_t dst_off) {
        const char* g = s + (size_t)(tb - HALO) * 128;
        for (int i = tid; i < STRIP_PX * 8; i += 256) {
            int px = i >> 3;
            int c = (i & 7) << 4;
            uint32_t sw = (uint32_t)(px * 128 + (c ^ ((px & 7) << 4)));
            cp16(sb + dst_off + sw, g + (size_t)px * 128 + c);
        }
    };
    auto stage_w = [&](int mod) {
        const char* wsrc = (const char*)g_wH + (size_t)mod * 73728;
        for (int g = tid; g < 4608; g += 256) {
            int o = g * 16;
            int sw = o ^ ((o >> 3) & 0x70);
            cp16(sb + SW_OFF + sw, wsrc + o);
        }
    };

    {
        const int img0 = j / TILES;
        const int tile0 = j - img0 * TILES;
        const int t0 = img0 >> 3;
        stage_w(layer * Mm + g_sel[t0*Ll + layer]);
        stage(src(img0), tile0 * TILE_M, SA0_OFF);
        cp_commit();
    }
    int cur_mod_t = (j / TILES) >> 3;

    for (int jj = 0; jj < nj; jj++, j++) {
        const int img = j / TILES;
        const int tile = j - img * TILES;
        const int t = img >> 3;
        const int tb = tile * TILE_M;
        const int mod = layer * Mm + g_sel[t*Ll + layer];
        const uint32_t abuf = sb + ((jj & 1) ? SA1_OFF : SA0_OFF);

        bool has_next = (jj + 1 < nj);
        int t2 = 0;
        bool mod_sw = false;
        if (has_next) {
            int j2 = j + 1;
            int img2 = j2 / TILES;
            int ntb = (j2 - img2 * TILES) * TILE_M;
            t2 = img2 >> 3;
            mod_sw = (t2 != cur_mod_t) &&
                     (g_sel[t2*Ll + layer] != g_sel[cur_mod_t*Ll + layer]);
            cp_wait<0>();
            __syncthreads();                 // A(cur)+W ready; buf(next) free
            stage(src(img2), ntb, (jj & 1) ? SA0_OFF : SA1_OFF);
            cp_commit();
        } else {
            cp_wait<0>();
            __syncthreads();
        }

        float acc[4][4][4];
        #pragma unroll
        for (int mt = 0; mt < 4; mt++)
            #pragma unroll
            for (int nt = 0; nt < 4; nt++)
                #pragma unroll
                for (int r = 0; r < 4; r++) acc[mt][nt][r] = 0.f;

        conv_pass(acc, sb, abuf, lane, wm, wn);

        const int g = lane >> 2, c2 = (lane & 3) * 2;
        const float* bb = enc_b + mod * 64;

        if (layer != 3) {
            __half* dst = g_act[pd] + ((size_t)img * PTOT + FRONT) * Cc;
            #pragma unroll
            for (int mt = 0; mt < 4; mt++) {
                #pragma unroll
                for (int r = 0; r < 2; r++) {
                    int row = wm * 64 + mt * 16 + g + r * 8;
                    int p = tb + row;
                    if (p < PPX) {
                        int y = p / PW, xx = p - y * PW;
                        if (y >= 1 && y <= Hh && xx >= 1 && xx <= Ww) {
                            size_t base = (size_t)p * Cc;
                            #pragma unroll
                            for (int nt = 0; nt < 4; nt++) {
                                int oc = wn * 32 + nt * 8 + c2;
                                float f0 = fmaxf(acc[mt][nt][r*2+0] + __ldg(bb + oc),     0.f);
                                float f1 = fmaxf(acc[mt][nt][r*2+1] + __ldg(bb + oc + 1), 0.f);
                                __half2 h = __floats2half2_rn(f0, f1);
                                *(uint32_t*)(dst + base + oc) = *reinterpret_cast<uint32_t*>(&h);
                            }
                        }
                    }
                }
            }
        } else {
            // fused decoder
            __shared__ float dbuf[TILE_M][2][3];
            float wd[3][8];
            #pragma unroll
            for (int kk = 0; kk < 3; kk++)
                #pragma unroll
                for (int q = 0; q < 8; q++) {
                    int oc = wn * 32 + (q >> 1) * 8 + c2 + (q & 1);
                    wd[kk][q] = __ldg(dec_w + ((size_t)t * 3 + kk) * 64 + oc);
                }
            #pragma unroll
            for (int mt = 0; mt < 4; mt++) {
                #pragma unroll
                for (int r = 0; r < 2; r++) {
                    float p0 = 0.f, p1 = 0.f, p2 = 0.f;
                    #pragma unroll
                    for (int nt = 0; nt < 4; nt++) {
                        int oc = wn * 32 + nt * 8 + c2;
                        float f0 = fmaxf(acc[mt][nt][r*2+0] + __ldg(bb + oc),     0.f);
                        float f1 = fmaxf(acc[mt][nt][r*2+1] + __ldg(bb + oc + 1), 0.f);
                        p0 = fmaf(f0, wd[0][nt*2+0], fmaf(f1, wd[0][nt*2+1], p0));
                        p1 = fmaf(f0, wd[1][nt*2+0], fmaf(f1, wd[1][nt*2+1], p1));
                        p2 = fmaf(f0, wd[2][nt*2+0], fmaf(f1, wd[2][nt*2+1], p2));
                    }
                    #pragma unroll
                    for (int off = 1; off < 4; off <<= 1) {
                        p0 += __shfl_xor_sync(0xffffffffu, p0, off);
                        p1 += __shfl_xor_sync(0xffffffffu, p1, off);
                        p2 += __shfl_xor_sync(0xffffffffu, p2, off);
                    }
                    if ((lane & 3) == 0) {
                        int pix = wm * 64 + mt * 16 + r * 8 + g;
                        dbuf[pix][wn][0] = p0;
                        dbuf[pix][wn][1] = p1;
                        dbuf[pix][wn][2] = p2;
                    }
                }
            }
            __syncthreads();
            {
                int p = tb + tid;
                if (p < PPX) {
                    int y = p / PW, xx = p - y * PW;
                    if (y >= 1 && y <= Hh && xx >= 1 && xx <= Ww) {
                        float a0 = dbuf[tid][0][0] + dbuf[tid][1][0] + __ldg(dec_b + t*3 + 0);
                        float a1 = dbuf[tid][0][1] + dbuf[tid][1][1] + __ldg(dec_b + t*3 + 1);
                        float a2 = dbuf[tid][0][2] + dbuf[tid][1][2] + __ldg(dec_b + t*3 + 2);
                        if (t == 2) {
                            float n = rsqrtf(a0*a0 + a1*a1 + a2*a2);
                            a0 *= n; a1 *= n; a2 *= n;
                        }
                        float* op = out + ((size_t)img * 3) * HWp + (y - 1) * Ww + (xx - 1);
                        op[0] = a0;
                        op[HWp] = a1;
                        op[2*HWp] = a2;
                    }
                }
            }
        }

        if (has_next && mod_sw) {
            __syncthreads();
            stage_w(layer * Mm + g_sel[t2*Ll + layer]);
            cp_commit();
        }
        if (has_next) cur_mod_t = t2;
    }
}

extern "C" void kernel_launch(void* const* d_in, const int* in_sizes, int n_in,
                              void* d_out, int out_size) {
    const float* x      = (const float*)d_in[0];
    const float* alpha0 = (const float*)d_in[1];
    const float* alphas = (const float*)d_in[2];
    const float* g0     = (const float*)d_in[3];
    const float* gs     = (const float*)d_in[4];
    const float* enc_w  = (const float*)d_in[5];
    const float* enc_b  = (const float*)d_in[6];
    const float* dec_w  = (const float*)d_in[7];
    const float* dec_b  = (const float*)d_in[8];
    float* out = (float*)d_out;

    cudaFuncSetAttribute(conv_hmma, cudaFuncAttributeMaxDynamicSharedMemorySize, SMEM_TOT);

    prep_kernel<<<2110, 256>>>(x, alpha0, alphas, g0, gs, enc_w);

    conv_hmma<<<CTAS, 256, SMEM_TOT>>>(0, 1, 0, 0, enc_b, dec_w, dec_b, out);
    conv_hmma<<<CTAS, 256, SMEM_TOT>>>(1, 0, 0, 1, enc_b, dec_w, dec_b, out);
    conv_hmma<<<CTAS, 256, SMEM_TOT>>>(2, 0, 1, 0, enc_b, dec_w, dec_b, out);
    conv_hmma<<<CTAS, 256, SMEM_TOT>>>(3, 0, 0, 1, enc_b, dec_w, dec_b, out);
}